// round 2
// baseline (speedup 1.0000x reference)
#include <cuda_runtime.h>

typedef unsigned long long ull_t;

#define N_ROWS 12288
#define Z_D 128
#define H_D 256
#define N_STEPS 8
#define DT_F 0.125f
#define P_ODE 97
#define P_DEC 65

// ---------------- global scratch (no allocations allowed) ----------------
__device__ float g_k[6][N_ROWS * Z_D];
__device__ float g_y[N_ROWS * Z_D];
__device__ float g_h[N_ROWS * H_D];
__device__ float g_s[N_ROWS * H_D];

// ---------------- dopri5 tableau ----------------
__constant__ float cA[6][5] = {
  {0.f, 0.f, 0.f, 0.f, 0.f},
  {0.2f, 0.f, 0.f, 0.f, 0.f},
  {3.f/40.f, 9.f/40.f, 0.f, 0.f, 0.f},
  {44.f/45.f, -56.f/15.f, 32.f/9.f, 0.f, 0.f},
  {19372.f/6561.f, -25360.f/2187.f, 64448.f/6561.f, -212.f/729.f, 0.f},
  {9017.f/3168.f, -355.f/33.f, 46732.f/5247.f, 49.f/176.f, -5103.f/18656.f}
};
__constant__ float cC[6]  = {0.f, 0.2f, 0.3f, 0.8f, 8.f/9.f, 1.f};
__constant__ float cBW[6] = {35.f/384.f, 0.f, 500.f/1113.f, 125.f/192.f,
                             -2187.f/6784.f, 11.f/84.f};

// ---------------- packed f32x2 helpers ----------------
__device__ __forceinline__ ull_t pack2(float x, float y) {
  ull_t r; asm("mov.b64 %0, {%1, %2};" : "=l"(r) : "f"(x), "f"(y)); return r;
}
__device__ __forceinline__ float2 unpack2(ull_t v) {
  float2 f; asm("mov.b64 {%0, %1}, %2;" : "=f"(f.x), "=f"(f.y) : "l"(v)); return f;
}
__device__ __forceinline__ void ffma2(ull_t& d, ull_t a, ull_t b) {
  asm("fma.rn.f32x2 %0, %1, %2, %0;" : "+l"(d) : "l"(a), "l"(b));
}
__device__ __forceinline__ float tanh_fast(float x) {
  float e = __expf(2.f * x);
  return 1.f - __fdividef(2.f, e + 1.f);
}

extern __shared__ float smem[];

// ---------------- register-blocked GEMM over transposed smem A ----------------
// acc[r][c] += sum_k AT[k][r0+r] * W[k][c0+c]; W streamed via 8-row smem tile.
template<int K, int KREAL, int RW, int NC, int WN, int PITCH>
__device__ __forceinline__ void gemm_acc(
    const float* __restrict__ AT, const float* __restrict__ Wg,
    float* __restrict__ Wst, ull_t* acc, int r0, int c0, int tid)
{
  constexpr int NT  = K / 8;
  constexpr int C4  = WN / 4;
  constexpr int NF4 = (8 * WN) / (4 * 256);
  float4 pf[NF4];

  // stage tile 0
  #pragma unroll
  for (int q = 0; q < NF4; q++) {
    int idx = tid + q * 256;
    int row = idx / C4, c4 = idx % C4;
    if (row < KREAL) pf[q] = *(const float4*)(Wg + (size_t)row * WN + c4 * 4);
    else             pf[q] = make_float4(0.f, 0.f, 0.f, 0.f);
  }
  #pragma unroll
  for (int q = 0; q < NF4; q++) {
    int idx = tid + q * 256;
    int row = idx / C4, c4 = idx % C4;
    *(float4*)(Wst + row * WN + c4 * 4) = pf[q];
  }
  __syncthreads();

  #pragma unroll 1
  for (int kt = 0; kt < NT; kt++) {
    if (kt + 1 < NT) {
      #pragma unroll
      for (int q = 0; q < NF4; q++) {
        int idx = tid + q * 256;
        int row = idx / C4, c4 = idx % C4;
        int gr  = (kt + 1) * 8 + row;
        if (gr < KREAL) pf[q] = *(const float4*)(Wg + (size_t)gr * WN + c4 * 4);
        else            pf[q] = make_float4(0.f, 0.f, 0.f, 0.f);
      }
    }
    #pragma unroll
    for (int kk = 0; kk < 8; kk++) {
      int k = kt * 8 + kk;
      float a[RW];
      #pragma unroll
      for (int i = 0; i < RW; i++) a[i] = AT[k * PITCH + r0 + i];
      ull_t bb[NC / 2];
      const ull_t* wr = (const ull_t*)(Wst + kk * WN + c0);
      #pragma unroll
      for (int j = 0; j < NC / 2; j++) bb[j] = wr[j];
      #pragma unroll
      for (int i = 0; i < RW; i++) {
        ull_t aa = pack2(a[i], a[i]);
        #pragma unroll
        for (int j = 0; j < NC / 2; j++) ffma2(acc[i * (NC / 2) + j], aa, bb[j]);
      }
    }
    __syncthreads();
    if (kt + 1 < NT) {
      #pragma unroll
      for (int q = 0; q < NF4; q++) {
        int idx = tid + q * 256;
        int row = idx / C4, c4 = idx % C4;
        *(float4*)(Wst + row * WN + c4 * 4) = pf[q];
      }
      __syncthreads();
    }
  }
}

template<int RW, int NC>
__device__ __forceinline__ void init_bias(ull_t* acc, const float* __restrict__ bias, int c0) {
  #pragma unroll
  for (int j = 0; j < NC / 2; j++) {
    float2 b2 = *(const float2*)(bias + c0 + 2 * j);
    ull_t v = pack2(b2.x, b2.y);
    #pragma unroll
    for (int i = 0; i < RW; i++) acc[i * (NC / 2) + j] = v;
  }
}

// ---------------- persistent ODE kernel: 8 dopri5 steps fused ----------------
__global__ void __launch_bounds__(256, 1) ode_kernel(
    const float* __restrict__ z,  const float* __restrict__ ts,
    const float* __restrict__ w_t, const float* __restrict__ b_t,
    const float* __restrict__ W1, const float* __restrict__ b1,
    const float* __restrict__ W2, const float* __restrict__ b2,
    const float* __restrict__ W3, const float* __restrict__ b3)
{
  float* AT  = smem;                    // [256][P_ODE]
  float* y_s = AT + 256 * P_ODE;        // [96][128]
  float* Wst = y_s + 96 * Z_D;          // [8][256]
  float* rat = Wst + 8 * 256;           // [96]

  const int tid = threadIdx.x;
  const int R0  = blockIdx.x * 96;
  const int rg = tid & 15, cg = tid >> 4;
  const int r0 = rg * 6;

  for (int idx = tid; idx < 96 * Z_D; idx += 256) {
    int r = idx >> 7, k = idx & 127;
    y_s[idx] = z[((R0 + r) & 63) * Z_D + k];
  }
  if (tid < 96) rat[tid] = ts[R0 + tid];
  __syncthreads();

  for (int step = 0; step < N_STEPS; step++) {
    float s0 = step * DT_F;
    for (int st = 0; st < 6; st++) {
      float tst = s0 + cC[st] * DT_F;

      // build yi^T into AT
      for (int idx = tid; idx < 96 * Z_D; idx += 256) {
        int r = idx >> 7, k = idx & 127;
        float v = y_s[idx];
        for (int j = 0; j < st; j++)
          v += (DT_F * cA[st][j]) * g_k[j][(size_t)(R0 + r) * Z_D + k];
        v += __cosf(fmaf(tst * rat[r], w_t[k], b_t[k]));
        AT[k * P_ODE + r] = v;
      }
      __syncthreads();

      {   // layer 1: [96,128]@[128,256] -> tanh -> AT^T
        ull_t acc[48];
        init_bias<6, 16>(acc, b1, cg * 16);
        gemm_acc<128, 128, 6, 16, 256, P_ODE>(AT, W1, Wst, acc, r0, cg * 16, tid);
        #pragma unroll
        for (int i = 0; i < 6; i++)
          #pragma unroll
          for (int j = 0; j < 8; j++) {
            float2 v = unpack2(acc[i * 8 + j]);
            int c = cg * 16 + 2 * j;
            AT[c * P_ODE + r0 + i]       = tanh_fast(v.x);
            AT[(c + 1) * P_ODE + r0 + i] = tanh_fast(v.y);
          }
        __syncthreads();
      }
      {   // layer 2: [96,256]@[256,256] -> tanh -> AT^T
        ull_t acc[48];
        init_bias<6, 16>(acc, b2, cg * 16);
        gemm_acc<256, 256, 6, 16, 256, P_ODE>(AT, W2, Wst, acc, r0, cg * 16, tid);
        #pragma unroll
        for (int i = 0; i < 6; i++)
          #pragma unroll
          for (int j = 0; j < 8; j++) {
            float2 v = unpack2(acc[i * 8 + j]);
            int c = cg * 16 + 2 * j;
            AT[c * P_ODE + r0 + i]       = tanh_fast(v.x);
            AT[(c + 1) * P_ODE + r0 + i] = tanh_fast(v.y);
          }
        __syncthreads();
      }
      {   // layer 3: [96,256]@[256,128] * ratio -> g_k[st]
        ull_t acc[24];
        init_bias<6, 8>(acc, b3, cg * 8);
        gemm_acc<256, 256, 6, 8, 128, P_ODE>(AT, W3, Wst, acc, r0, cg * 8, tid);
        #pragma unroll
        for (int i = 0; i < 6; i++) {
          int r = r0 + i;
          float rr = rat[r];
          size_t base = (size_t)(R0 + r) * Z_D + cg * 8;
          #pragma unroll
          for (int j = 0; j < 4; j++) {
            float2 v = unpack2(acc[i * 4 + j]);
            v.x *= rr; v.y *= rr;
            *(float2*)(&g_k[st][base + 2 * j]) = v;
          }
        }
        __syncthreads();
      }
    }
    // y += dt * sum bw_j k_j
    for (int idx = tid; idx < 96 * Z_D; idx += 256) {
      int r = idx >> 7, k = idx & 127;
      size_t gi = (size_t)(R0 + r) * Z_D + k;
      float v = y_s[idx];
      v += DT_F * (cBW[0] * g_k[0][gi] + cBW[2] * g_k[2][gi] + cBW[3] * g_k[3][gi]
                 + cBW[4] * g_k[4][gi] + cBW[5] * g_k[5][gi]);
      y_s[idx] = v;
    }
    __syncthreads();
  }

  for (int idx = tid; idx < 96 * Z_D; idx += 256) {
    int r = idx >> 7, k = idx & 127;
    g_y[(size_t)(R0 + r) * Z_D + k] = y_s[idx];
  }
}

// ---------------- decode_fc: [x | y_final] @ Wd + bd ----------------
__global__ void __launch_bounds__(256, 1) dec_kernel(
    const float* __restrict__ x, const float* __restrict__ Wd, const float* __restrict__ bd)
{
  float* AT  = smem;                   // [304][P_DEC]
  float* Wst = AT + 304 * P_DEC;
  const int tid = threadIdx.x;
  const int R0  = blockIdx.x * 64;
  const int rg = tid & 15, cg = tid >> 4;
  const float* xr = x + (size_t)blockIdx.x * 172;

  for (int idx = tid; idx < 304 * 64; idx += 256) {
    int c = idx >> 6, r = idx & 63;
    float v = 0.f;
    if (c < 172) v = xr[c];
    else if (c < 300) v = g_y[(size_t)(R0 + r) * Z_D + (c - 172)];
    AT[c * P_DEC + r] = v;
  }
  __syncthreads();

  ull_t acc[32];
  init_bias<4, 16>(acc, bd, cg * 16);
  gemm_acc<304, 300, 4, 16, 256, P_DEC>(AT, Wd, Wst, acc, rg * 4, cg * 16, tid);
  #pragma unroll
  for (int i = 0; i < 4; i++) {
    size_t base = (size_t)(R0 + rg * 4 + i) * H_D + cg * 16;
    #pragma unroll
    for (int j = 0; j < 8; j++) {
      float2 v = unpack2(acc[i * 8 + j]);
      *(float2*)(&g_h[base + 2 * j]) = v;
    }
  }
}

// ---------------- src/dst fc ----------------
__global__ void __launch_bounds__(256, 1) sd_kernel(
    const float* __restrict__ Ws, const float* __restrict__ bs,
    const float* __restrict__ Wdst, const float* __restrict__ bdst)
{
  float* AT  = smem;                   // [256][P_DEC]
  float* Wst = AT + 256 * P_DEC;
  const int tid = threadIdx.x;
  const int R0  = blockIdx.x * 64;
  const int rg = tid & 15, cg = tid >> 4;
  const float* W = (R0 < 4096) ? Ws : Wdst;
  const float* bb = (R0 < 4096) ? bs : bdst;

  for (int idx = tid; idx < 256 * 64; idx += 256) {
    int c = idx >> 6, r = idx & 63;
    AT[c * P_DEC + r] = g_h[(size_t)(R0 + r) * H_D + c];
  }
  __syncthreads();

  ull_t acc[32];
  init_bias<4, 16>(acc, bb, cg * 16);
  gemm_acc<256, 256, 4, 16, 256, P_DEC>(AT, W, Wst, acc, rg * 4, cg * 16, tid);
  #pragma unroll
  for (int i = 0; i < 4; i++) {
    size_t base = (size_t)(R0 + rg * 4 + i) * H_D + cg * 16;
    #pragma unroll
    for (int j = 0; j < 8; j++) {
      float2 v = unpack2(acc[i * 8 + j]);
      *(float2*)(&g_s[base + 2 * j]) = v;
    }
  }
}

// ---------------- edge out + mean over L ----------------
__global__ void __launch_bounds__(256) edge_kernel(
    const float* __restrict__ Wo, const float* __restrict__ bo, float* __restrict__ out)
{
  __shared__ float red[8];
  const int tid = threadIdx.x;
  const int o = blockIdx.x;
  const int b = (o < 64) ? o : (o - 64);
  const size_t off2 = (o < 64) ? (size_t)4096 * H_D : (size_t)8192 * H_D;
  const float wcol = Wo[tid];

  float sum = 0.f;
  for (int l = 0; l < 64; l++) {
    size_t r1 = (size_t)(b * 64 + l) * H_D + tid;
    float v = g_s[r1] + g_s[off2 + r1];
    sum += fmaxf(v, 0.f) * wcol;
  }
  #pragma unroll
  for (int d = 16; d > 0; d >>= 1) sum += __shfl_xor_sync(0xFFFFFFFFu, sum, d);
  if ((tid & 31) == 0) red[tid >> 5] = sum;
  __syncthreads();
  if (tid == 0) {
    float t = 0.f;
    #pragma unroll
    for (int w = 0; w < 8; w++) t += red[w];
    out[o] = t * (1.f / 64.f) + bo[0];
  }
}

extern "C" void kernel_launch(void* const* d_in, const int* in_sizes, int n_in,
                              void* d_out, int out_size) {
  const float* x    = (const float*)d_in[0];
  const float* z    = (const float*)d_in[1];
  const float* ts   = (const float*)d_in[2];
  const float* w_t  = (const float*)d_in[3];
  const float* b_t  = (const float*)d_in[4];
  const float* W1   = (const float*)d_in[5];
  const float* b1   = (const float*)d_in[6];
  const float* W2   = (const float*)d_in[7];
  const float* b2   = (const float*)d_in[8];
  const float* W3   = (const float*)d_in[9];
  const float* b3   = (const float*)d_in[10];
  const float* Wd   = (const float*)d_in[11];
  const float* bd   = (const float*)d_in[12];
  const float* Ws   = (const float*)d_in[13];
  const float* bs   = (const float*)d_in[14];
  const float* Wdst = (const float*)d_in[15];
  const float* bdst = (const float*)d_in[16];
  const float* Wo   = (const float*)d_in[17];
  const float* bo   = (const float*)d_in[18];
  float* out = (float*)d_out;

  const int SM_ODE = (256 * P_ODE + 96 * Z_D + 8 * 256 + 96) * 4;
  const int SM_D1  = (304 * P_DEC + 8 * 256) * 4;
  const int SM_D2  = (256 * P_DEC + 8 * 256) * 4;

  cudaFuncSetAttribute(ode_kernel, cudaFuncAttributeMaxDynamicSharedMemorySize, SM_ODE);
  cudaFuncSetAttribute(dec_kernel, cudaFuncAttributeMaxDynamicSharedMemorySize, SM_D1);
  cudaFuncSetAttribute(sd_kernel,  cudaFuncAttributeMaxDynamicSharedMemorySize, SM_D2);

  ode_kernel<<<128, 256, SM_ODE>>>(z, ts, w_t, b_t, W1, b1, W2, b2, W3, b3);
  dec_kernel<<<192, 256, SM_D1>>>(x, Wd, bd);
  sd_kernel<<<192, 256, SM_D2>>>(Ws, bs, Wdst, bdst);
  edge_kernel<<<128, 256>>>(Wo, bo, out);
}